// round 2
// baseline (speedup 1.0000x reference)
#include <cuda_runtime.h>
#include <cuda_fp16.h>
#include <stdint.h>

// Problem constants (fixed by setup_inputs)
#define NQ   100000
#define HN   32      // neighbors per query
#define KP   15      // kernel points
#define CIN  64
#define COUT 128
#define KC   (KP * CIN)   // 960
#define KP_EXT 1.2f
#define KP_EXT2 (KP_EXT * KP_EXT)   // 1.44

// Scratch (device globals: allocation-free)
__device__ __half g_weighted[(size_t)NQ * KC];   // [N][K*Cin] fp16, ~192 MB
__device__ __half g_wts[KC * COUT];              // [K*Cin][Cout] fp16

// ---------------------------------------------------------------------------
// Kernel 0: convert wts fp32 -> fp16
// ---------------------------------------------------------------------------
__global__ void convert_wts_kernel(const float* __restrict__ wts) {
    int i = blockIdx.x * blockDim.x + threadIdx.x;
    if (i < KC * COUT) g_wts[i] = __float2half(wts[i]);
}

// ---------------------------------------------------------------------------
// Kernel 1: per-query influence weights + sparse weighted feature aggregation
// One warp handles 4 queries. Lane l owns neighbor h=l for weight computation
// and channel pair (2l, 2l+1) for accumulation. Sparsity via per-k ballot.
//
// Distance via norm expansion: d2 = |p|^2 + |kp|^2 - 2 p.kp  (4 FMA/pair),
// sqrt predicated on d2 < KP_EXT^2 (~7.7% hit rate) to keep MUFU idle.
// ---------------------------------------------------------------------------
__global__ void __launch_bounds__(256) weight_kernel(
    const float* __restrict__ qpts,
    const float* __restrict__ spts,
    const int*   __restrict__ nidx,
    const float* __restrict__ feats,
    const float* __restrict__ kpts,
    int nq)
{
    __shared__ float4 skp[KP];   // (kx, ky, kz, |kp|^2)
    int tid = threadIdx.x;
    if (tid < KP) {
        float kx = kpts[3 * tid + 0];
        float ky = kpts[3 * tid + 1];
        float kz = kpts[3 * tid + 2];
        skp[tid] = make_float4(kx, ky, kz, kx * kx + ky * ky + kz * kz);
    }
    __syncthreads();

    int warp = tid >> 5;
    int lane = tid & 31;
    const float inv_ext = 1.0f / KP_EXT;
    int qbase = blockIdx.x * 32 + warp * 4;

    const float2* __restrict__ f2 = (const float2*)feats;
    __half2* outp = (__half2*)g_weighted;

    #pragma unroll 1
    for (int qi = 0; qi < 4; qi++) {
        int q = qbase + qi;
        if (q >= nq) return;   // warp-uniform

        // Each lane: neighbor h = lane
        int idx = nidx[q * HN + lane];
        float qx = qpts[q * 3 + 0];
        float qy = qpts[q * 3 + 1];
        float qz = qpts[q * 3 + 2];
        float px = spts[idx * 3 + 0] - qx;
        float py = spts[idx * 3 + 1] - qy;
        float pz = spts[idx * 3 + 2] - qz;
        float pp = px * px + py * py + pz * pz;

        float    w[KP];
        unsigned m[KP];
        #pragma unroll
        for (int k = 0; k < KP; k++) {
            float4 kv = skp[k];
            float t  = fmaf(px, kv.x, fmaf(py, kv.y, pz * kv.z));
            float d2 = fmaf(-2.0f, t, pp + kv.w);
            float wv = 0.0f;
            if (d2 < KP_EXT2)
                wv = 1.0f - sqrtf(fmaxf(d2, 0.0f)) * inv_ext;
            w[k] = wv;
            m[k] = __ballot_sync(0xffffffffu, wv > 0.0f);
        }

        // k outer (unrolled, register accumulators), inner loop over the
        // active neighbors of this kernel point only (~2.5 avg of 32).
        #pragma unroll
        for (int k = 0; k < KP; k++) {
            float ax = 0.0f, ay = 0.0f;
            unsigned mm = m[k];
            while (mm) {
                int h = __ffs(mm) - 1;
                mm &= mm - 1;
                float wk = __shfl_sync(0xffffffffu, w[k], h);
                int   ih = __shfl_sync(0xffffffffu, idx,  h);
                float2 f = f2[(size_t)ih * 32 + lane];   // channels (2l, 2l+1)
                ax = fmaf(wk, f.x, ax);
                ay = fmaf(wk, f.y, ay);
            }
            // weighted[q][k*64 + 2l .. 2l+1]
            outp[(size_t)q * (KC / 2) + k * 32 + lane] = __floats2half2_rn(ax, ay);
        }
    }
}

// ---------------------------------------------------------------------------
// Kernel 2: GEMM  out[N][128] = weighted[N][960] (f16) x wts[960][128] (f16)
// Block tile 128x128, k-stage 32, 8 warps each 64x32 via m16n8k16 HMMA.
// ---------------------------------------------------------------------------
__device__ __forceinline__ void ldm_x4(uint32_t& r0, uint32_t& r1,
                                       uint32_t& r2, uint32_t& r3,
                                       uint32_t addr) {
    asm volatile("ldmatrix.sync.aligned.m8n8.x4.shared.b16 {%0,%1,%2,%3}, [%4];"
                 : "=r"(r0), "=r"(r1), "=r"(r2), "=r"(r3) : "r"(addr));
}
__device__ __forceinline__ void ldm_x4_t(uint32_t& r0, uint32_t& r1,
                                         uint32_t& r2, uint32_t& r3,
                                         uint32_t addr) {
    asm volatile("ldmatrix.sync.aligned.m8n8.x4.trans.shared.b16 {%0,%1,%2,%3}, [%4];"
                 : "=r"(r0), "=r"(r1), "=r"(r2), "=r"(r3) : "r"(addr));
}
__device__ __forceinline__ void mma16816(float& c0, float& c1, float& c2, float& c3,
                                         uint32_t a0, uint32_t a1, uint32_t a2, uint32_t a3,
                                         uint32_t b0, uint32_t b1) {
    asm volatile(
        "mma.sync.aligned.m16n8k16.row.col.f32.f16.f16.f32 "
        "{%0,%1,%2,%3}, {%4,%5,%6,%7}, {%8,%9}, {%0,%1,%2,%3};"
        : "+f"(c0), "+f"(c1), "+f"(c2), "+f"(c3)
        : "r"(a0), "r"(a1), "r"(a2), "r"(a3), "r"(b0), "r"(b1));
}

#define AS_STRIDE 48    // halves per A row (32 data + 16 pad, keeps 16B align)
#define BS_STRIDE 136   // halves per B row (128 data + 8 pad)

__global__ void __launch_bounds__(256) gemm_kernel(float* __restrict__ out, int nq) {
    __shared__ __half As[128 * AS_STRIDE];
    __shared__ __half Bs[32 * BS_STRIDE];

    int tid  = threadIdx.x;
    int wid  = tid >> 5;
    int lane = tid & 31;
    int wm = wid >> 2;   // 0..1  (64 rows each)
    int wn = wid & 3;    // 0..3  (32 cols each)
    int m0 = blockIdx.x * 128;

    float c[4][4][4];
    #pragma unroll
    for (int i = 0; i < 4; i++)
        #pragma unroll
        for (int j = 0; j < 4; j++)
            #pragma unroll
            for (int t = 0; t < 4; t++) c[i][j][t] = 0.0f;

    int lrow  = lane & 15;
    int lcolh = (lane >> 4) * 8;

    for (int kt = 0; kt < KC / 32; kt++) {
        // Stage A tile [128][32] f16 (2 x uint4 per thread)
        #pragma unroll
        for (int i = 0; i < 2; i++) {
            int chunk = tid + i * 256;            // 0..511
            int row = chunk >> 2, seg = chunk & 3;
            int rg = m0 + row;
            uint4 v = make_uint4(0u, 0u, 0u, 0u);
            if (rg < nq)
                v = *(const uint4*)(g_weighted + (size_t)rg * KC + kt * 32 + seg * 8);
            *(uint4*)(As + row * AS_STRIDE + seg * 8) = v;
        }
        // Stage B tile [32][128] f16 (2 x uint4 per thread)
        #pragma unroll
        for (int i = 0; i < 2; i++) {
            int chunk = tid + i * 256;
            int row = chunk >> 4, seg = chunk & 15;
            uint4 v = *(const uint4*)(g_wts + (kt * 32 + row) * COUT + seg * 8);
            *(uint4*)(Bs + row * BS_STRIDE + seg * 8) = v;
        }
        __syncthreads();

        #pragma unroll
        for (int ks = 0; ks < 2; ks++) {
            uint32_t a[4][4], b[4][2];
            #pragma unroll
            for (int im = 0; im < 4; im++) {
                uint32_t addr = (uint32_t)__cvta_generic_to_shared(
                    As + (wm * 64 + im * 16 + lrow) * AS_STRIDE + ks * 16 + lcolh);
                ldm_x4(a[im][0], a[im][1], a[im][2], a[im][3], addr);
            }
            #pragma unroll
            for (int ip = 0; ip < 2; ip++) {
                uint32_t addr = (uint32_t)__cvta_generic_to_shared(
                    Bs + (ks * 16 + lrow) * BS_STRIDE + wn * 32 + ip * 16 + lcolh);
                uint32_t r0, r1, r2, r3;
                ldm_x4_t(r0, r1, r2, r3, addr);
                b[ip * 2 + 0][0] = r0; b[ip * 2 + 0][1] = r1;
                b[ip * 2 + 1][0] = r2; b[ip * 2 + 1][1] = r3;
            }
            #pragma unroll
            for (int im = 0; im < 4; im++)
                #pragma unroll
                for (int in = 0; in < 4; in++)
                    mma16816(c[im][in][0], c[im][in][1], c[im][in][2], c[im][in][3],
                             a[im][0], a[im][1], a[im][2], a[im][3],
                             b[in][0], b[in][1]);
        }
        __syncthreads();
    }

    // Epilogue
    int gid = lane >> 2, tig = lane & 3;
    #pragma unroll
    for (int im = 0; im < 4; im++) {
        #pragma unroll
        for (int in = 0; in < 4; in++) {
            int row = m0 + wm * 64 + im * 16 + gid;
            int col = wn * 32 + in * 8 + tig * 2;
            if (row < nq) {
                float2 v0 = make_float2(c[im][in][0], c[im][in][1]);
                *(float2*)(out + (size_t)row * COUT + col) = v0;
            }
            if (row + 8 < nq) {
                float2 v1 = make_float2(c[im][in][2], c[im][in][3]);
                *(float2*)(out + (size_t)(row + 8) * COUT + col) = v1;
            }
        }
    }
}

// ---------------------------------------------------------------------------
extern "C" void kernel_launch(void* const* d_in, const int* in_sizes, int n_in,
                              void* d_out, int out_size) {
    const float* qp = (const float*)d_in[0];   // query_points   [N,3]
    const float* sp = (const float*)d_in[1];   // support_points [M,3]
    const int*   ni = (const int*)  d_in[2];   // neighbors_idx  [N,32]
    const float* ft = (const float*)d_in[3];   // features       [M,64]
    const float* kp = (const float*)d_in[4];   // kernel_points  [15,3]
    const float* wt = (const float*)d_in[5];   // wts            [15,64,128]
    float* out = (float*)d_out;

    int nq = in_sizes[0] / 3;

    convert_wts_kernel<<<(KC * COUT + 255) / 256, 256>>>(wt);
    weight_kernel<<<(nq + 31) / 32, 256>>>(qp, sp, ni, ft, kp, nq);
    gemm_kernel<<<(nq + 127) / 128, 256>>>(out, nq);
}

// round 3
// speedup vs baseline: 1.3290x; 1.3290x over previous
#include <cuda_runtime.h>
#include <cuda_fp16.h>
#include <stdint.h>

// Problem constants (fixed by setup_inputs)
#define NQ   100000
#define HN   32      // neighbors per query
#define KP   15      // kernel points
#define CIN  64
#define COUT 128
#define KC   (KP * CIN)   // 960
#define KP_EXT 1.2f
#define KP_EXT2 (KP_EXT * KP_EXT)   // 1.44

// Scratch (device globals: allocation-free)
__device__ __half g_weighted[(size_t)NQ * KC];   // [N][K*Cin] fp16, ~192 MB
__device__ __half g_wts[KC * COUT];              // [K*Cin][Cout] fp16

// ---------------------------------------------------------------------------
// Kernel 0: convert wts fp32 -> fp16
// ---------------------------------------------------------------------------
__global__ void convert_wts_kernel(const float* __restrict__ wts) {
    int i = blockIdx.x * blockDim.x + threadIdx.x;
    if (i < KC * COUT) g_wts[i] = __float2half(wts[i]);
}

// ---------------------------------------------------------------------------
// Kernel 1: weights + sparse weighted feature aggregation, two-phase.
//
// Phase A (stage): warp cooperatively gathers active neighbors' feature rows
//   into smem with MLP~32 (coalesced 256B rows), killing the L2-latency
//   serial chain that bound rounds 1-2.
// Phase B (accumulate): sparse per-k bit-loop reads from smem (29-cyc LDS)
//   instead of L2 (260-cyc LDG).
//
// Block = 128 threads = 4 warps; 8KB fp32 feature stage per warp (32KB static).
// ---------------------------------------------------------------------------
__global__ void __launch_bounds__(128) weight_kernel(
    const float* __restrict__ qpts,
    const float* __restrict__ spts,
    const int*   __restrict__ nidx,
    const float* __restrict__ feats,
    const float* __restrict__ kpts,
    int nq)
{
    __shared__ float2 Fs[4][HN * 32];   // [warp][h][c-pair]  4*8KB = 32KB
    __shared__ float4 skp[KP];          // (kx, ky, kz, |kp|^2)

    int tid = threadIdx.x;
    if (tid < KP) {
        float kx = kpts[3 * tid + 0];
        float ky = kpts[3 * tid + 1];
        float kz = kpts[3 * tid + 2];
        skp[tid] = make_float4(kx, ky, kz, kx * kx + ky * ky + kz * kz);
    }
    __syncthreads();

    int warp = tid >> 5;
    int lane = tid & 31;
    const float inv_ext = 1.0f / KP_EXT;
    int qbase = blockIdx.x * 16 + warp * 4;

    const float2* __restrict__ f2 = (const float2*)feats;
    float2* FsW = Fs[warp];
    __half2* outp = (__half2*)g_weighted;

    #pragma unroll 1
    for (int qi = 0; qi < 4; qi++) {
        int q = qbase + qi;
        if (q >= nq) return;   // warp-uniform

        // ---- weights: lane owns neighbor h = lane ----
        int idx = nidx[q * HN + lane];
        float qx = qpts[q * 3 + 0];
        float qy = qpts[q * 3 + 1];
        float qz = qpts[q * 3 + 2];
        float px = spts[idx * 3 + 0] - qx;
        float py = spts[idx * 3 + 1] - qy;
        float pz = spts[idx * 3 + 2] - qz;
        float pp = px * px + py * py + pz * pz;

        float    w[KP];
        unsigned m[KP];
        unsigned active_h = 0;
        #pragma unroll
        for (int k = 0; k < KP; k++) {
            float4 kv = skp[k];
            float t  = fmaf(px, kv.x, fmaf(py, kv.y, pz * kv.z));
            float d2 = fmaf(-2.0f, t, pp + kv.w);
            float wv = 0.0f;
            if (d2 < KP_EXT2)
                wv = 1.0f - sqrtf(fmaxf(d2, 0.0f)) * inv_ext;
            w[k] = wv;
            m[k] = __ballot_sync(0xffffffffu, wv > 0.0f);
            active_h |= m[k];
        }

        // ---- Phase A: stage active neighbor features (MLP ~32) ----
        __syncwarp();
        #pragma unroll
        for (int h = 0; h < HN; h++) {
            if ((active_h >> h) & 1u) {               // warp-uniform predicate
                int ih = __shfl_sync(0xffffffffu, idx, h);
                FsW[h * 32 + lane] = f2[(size_t)ih * 32 + lane];
            }
        }
        __syncwarp();

        // ---- Phase B: sparse per-k accumulation from smem ----
        #pragma unroll
        for (int k = 0; k < KP; k++) {
            float ax = 0.0f, ay = 0.0f;
            unsigned mm = m[k];
            while (mm) {
                int h = __ffs(mm) - 1;
                mm &= mm - 1;
                float wk = __shfl_sync(0xffffffffu, w[k], h);
                float2 f = FsW[h * 32 + lane];
                ax = fmaf(wk, f.x, ax);
                ay = fmaf(wk, f.y, ay);
            }
            outp[(size_t)q * (KC / 2) + k * 32 + lane] = __floats2half2_rn(ax, ay);
        }
    }
}

// ---------------------------------------------------------------------------
// Kernel 2: GEMM  out[N][128] = weighted[N][960] (f16) x wts[960][128] (f16)
// Block tile 128x128, k-stage 32, 8 warps each 64x32 via m16n8k16 HMMA.
// ---------------------------------------------------------------------------
__device__ __forceinline__ void ldm_x4(uint32_t& r0, uint32_t& r1,
                                       uint32_t& r2, uint32_t& r3,
                                       uint32_t addr) {
    asm volatile("ldmatrix.sync.aligned.m8n8.x4.shared.b16 {%0,%1,%2,%3}, [%4];"
                 : "=r"(r0), "=r"(r1), "=r"(r2), "=r"(r3) : "r"(addr));
}
__device__ __forceinline__ void ldm_x4_t(uint32_t& r0, uint32_t& r1,
                                         uint32_t& r2, uint32_t& r3,
                                         uint32_t addr) {
    asm volatile("ldmatrix.sync.aligned.m8n8.x4.trans.shared.b16 {%0,%1,%2,%3}, [%4];"
                 : "=r"(r0), "=r"(r1), "=r"(r2), "=r"(r3) : "r"(addr));
}
__device__ __forceinline__ void mma16816(float& c0, float& c1, float& c2, float& c3,
                                         uint32_t a0, uint32_t a1, uint32_t a2, uint32_t a3,
                                         uint32_t b0, uint32_t b1) {
    asm volatile(
        "mma.sync.aligned.m16n8k16.row.col.f32.f16.f16.f32 "
        "{%0,%1,%2,%3}, {%4,%5,%6,%7}, {%8,%9}, {%0,%1,%2,%3};"
        : "+f"(c0), "+f"(c1), "+f"(c2), "+f"(c3)
        : "r"(a0), "r"(a1), "r"(a2), "r"(a3), "r"(b0), "r"(b1));
}

#define AS_STRIDE 48    // halves per A row (32 data + 16 pad, keeps 16B align)
#define BS_STRIDE 136   // halves per B row (128 data + 8 pad)

__global__ void __launch_bounds__(256) gemm_kernel(float* __restrict__ out, int nq) {
    __shared__ __half As[128 * AS_STRIDE];
    __shared__ __half Bs[32 * BS_STRIDE];

    int tid  = threadIdx.x;
    int wid  = tid >> 5;
    int lane = tid & 31;
    int wm = wid >> 2;   // 0..1  (64 rows each)
    int wn = wid & 3;    // 0..3  (32 cols each)
    int m0 = blockIdx.x * 128;

    float c[4][4][4];
    #pragma unroll
    for (int i = 0; i < 4; i++)
        #pragma unroll
        for (int j = 0; j < 4; j++)
            #pragma unroll
            for (int t = 0; t < 4; t++) c[i][j][t] = 0.0f;

    int lrow  = lane & 15;
    int lcolh = (lane >> 4) * 8;

    for (int kt = 0; kt < KC / 32; kt++) {
        // Stage A tile [128][32] f16 (2 x uint4 per thread)
        #pragma unroll
        for (int i = 0; i < 2; i++) {
            int chunk = tid + i * 256;            // 0..511
            int row = chunk >> 2, seg = chunk & 3;
            int rg = m0 + row;
            uint4 v = make_uint4(0u, 0u, 0u, 0u);
            if (rg < nq)
                v = *(const uint4*)(g_weighted + (size_t)rg * KC + kt * 32 + seg * 8);
            *(uint4*)(As + row * AS_STRIDE + seg * 8) = v;
        }
        // Stage B tile [32][128] f16 (2 x uint4 per thread)
        #pragma unroll
        for (int i = 0; i < 2; i++) {
            int chunk = tid + i * 256;
            int row = chunk >> 4, seg = chunk & 15;
            uint4 v = *(const uint4*)(g_wts + (kt * 32 + row) * COUT + seg * 8);
            *(uint4*)(Bs + row * BS_STRIDE + seg * 8) = v;
        }
        __syncthreads();

        #pragma unroll
        for (int ks = 0; ks < 2; ks++) {
            uint32_t a[4][4], b[4][2];
            #pragma unroll
            for (int im = 0; im < 4; im++) {
                uint32_t addr = (uint32_t)__cvta_generic_to_shared(
                    As + (wm * 64 + im * 16 + lrow) * AS_STRIDE + ks * 16 + lcolh);
                ldm_x4(a[im][0], a[im][1], a[im][2], a[im][3], addr);
            }
            #pragma unroll
            for (int ip = 0; ip < 2; ip++) {
                uint32_t addr = (uint32_t)__cvta_generic_to_shared(
                    Bs + (ks * 16 + lrow) * BS_STRIDE + wn * 32 + ip * 16 + lcolh);
                uint32_t r0, r1, r2, r3;
                ldm_x4_t(r0, r1, r2, r3, addr);
                b[ip * 2 + 0][0] = r0; b[ip * 2 + 0][1] = r1;
                b[ip * 2 + 1][0] = r2; b[ip * 2 + 1][1] = r3;
            }
            #pragma unroll
            for (int im = 0; im < 4; im++)
                #pragma unroll
                for (int in = 0; in < 4; in++)
                    mma16816(c[im][in][0], c[im][in][1], c[im][in][2], c[im][in][3],
                             a[im][0], a[im][1], a[im][2], a[im][3],
                             b[in][0], b[in][1]);
        }
        __syncthreads();
    }

    // Epilogue
    int gid = lane >> 2, tig = lane & 3;
    #pragma unroll
    for (int im = 0; im < 4; im++) {
        #pragma unroll
        for (int in = 0; in < 4; in++) {
            int row = m0 + wm * 64 + im * 16 + gid;
            int col = wn * 32 + in * 8 + tig * 2;
            if (row < nq) {
                float2 v0 = make_float2(c[im][in][0], c[im][in][1]);
                *(float2*)(out + (size_t)row * COUT + col) = v0;
            }
            if (row + 8 < nq) {
                float2 v1 = make_float2(c[im][in][2], c[im][in][3]);
                *(float2*)(out + (size_t)(row + 8) * COUT + col) = v1;
            }
        }
    }
}

// ---------------------------------------------------------------------------
extern "C" void kernel_launch(void* const* d_in, const int* in_sizes, int n_in,
                              void* d_out, int out_size) {
    const float* qp = (const float*)d_in[0];   // query_points   [N,3]
    const float* sp = (const float*)d_in[1];   // support_points [M,3]
    const int*   ni = (const int*)  d_in[2];   // neighbors_idx  [N,32]
    const float* ft = (const float*)d_in[3];   // features       [M,64]
    const float* kp = (const float*)d_in[4];   // kernel_points  [15,3]
    const float* wt = (const float*)d_in[5];   // wts            [15,64,128]
    float* out = (float*)d_out;

    int nq = in_sizes[0] / 3;

    convert_wts_kernel<<<(KC * COUT + 255) / 256, 256>>>(wt);
    weight_kernel<<<(nq + 15) / 16, 128>>>(qp, sp, ni, ft, kp, nq);
    gemm_kernel<<<(nq + 127) / 128, 256>>>(out, nq);
}

// round 5
// speedup vs baseline: 1.5361x; 1.1559x over previous
#include <cuda_runtime.h>
#include <cuda_fp16.h>
#include <stdint.h>

// Problem constants (fixed by setup_inputs)
#define NQ   100000
#define HN   32      // neighbors per query
#define KP   15      // kernel points
#define CIN  64
#define COUT 128
#define KC   (KP * CIN)   // 960
#define KP_EXT 1.2f
#define KP_EXT2 (KP_EXT * KP_EXT)   // 1.44

// Scratch (device globals: allocation-free)
__device__ __half g_weighted[(size_t)NQ * KC];   // [N][K*Cin] fp16, ~192 MB
__device__ __half g_wts[KC * COUT];              // [K*Cin][Cout] fp16

__device__ __forceinline__ uint32_t smem_u32(const void* p) {
    uint32_t a;
    asm("{ .reg .u64 t; cvta.to.shared.u64 t, %1; cvt.u32.u64 %0, t; }"
        : "=r"(a) : "l"(p));
    return a;
}

// ---------------------------------------------------------------------------
// Kernel 0: convert wts fp32 -> fp16
// ---------------------------------------------------------------------------
__global__ void convert_wts_kernel(const float* __restrict__ wts) {
    int i = blockIdx.x * blockDim.x + threadIdx.x;
    if (i < KC * COUT) g_wts[i] = __float2half(wts[i]);
}

// ---------------------------------------------------------------------------
// Kernel 1: weights + sparse weighted feature aggregation (round-3 version).
// Launched FIRST so ncu (-s 5 -c 1, first kernel in sequence) profiles it.
// ---------------------------------------------------------------------------
__global__ void __launch_bounds__(128) weight_kernel(
    const float* __restrict__ qpts,
    const float* __restrict__ spts,
    const int*   __restrict__ nidx,
    const float* __restrict__ feats,
    const float* __restrict__ kpts,
    int nq)
{
    __shared__ float2 Fs[4][HN * 32];   // [warp][h][c-pair]  4*8KB = 32KB
    __shared__ float4 skp[KP];          // (kx, ky, kz, |kp|^2)

    int tid = threadIdx.x;
    if (tid < KP) {
        float kx = kpts[3 * tid + 0];
        float ky = kpts[3 * tid + 1];
        float kz = kpts[3 * tid + 2];
        skp[tid] = make_float4(kx, ky, kz, kx * kx + ky * ky + kz * kz);
    }
    __syncthreads();

    int warp = tid >> 5;
    int lane = tid & 31;
    const float inv_ext = 1.0f / KP_EXT;
    int qbase = blockIdx.x * 16 + warp * 4;

    const float2* __restrict__ f2 = (const float2*)feats;
    float2* FsW = Fs[warp];
    __half2* outp = (__half2*)g_weighted;

    #pragma unroll 1
    for (int qi = 0; qi < 4; qi++) {
        int q = qbase + qi;
        if (q >= nq) return;   // warp-uniform

        int idx = nidx[q * HN + lane];
        float qx = qpts[q * 3 + 0];
        float qy = qpts[q * 3 + 1];
        float qz = qpts[q * 3 + 2];
        float px = spts[idx * 3 + 0] - qx;
        float py = spts[idx * 3 + 1] - qy;
        float pz = spts[idx * 3 + 2] - qz;
        float pp = px * px + py * py + pz * pz;

        float    w[KP];
        unsigned m[KP];
        unsigned active_h = 0;
        #pragma unroll
        for (int k = 0; k < KP; k++) {
            float4 kv = skp[k];
            float t  = fmaf(px, kv.x, fmaf(py, kv.y, pz * kv.z));
            float d2 = fmaf(-2.0f, t, pp + kv.w);
            float wv = 0.0f;
            if (d2 < KP_EXT2)
                wv = 1.0f - sqrtf(fmaxf(d2, 0.0f)) * inv_ext;
            w[k] = wv;
            m[k] = __ballot_sync(0xffffffffu, wv > 0.0f);
            active_h |= m[k];
        }

        __syncwarp();
        #pragma unroll
        for (int h = 0; h < HN; h++) {
            if ((active_h >> h) & 1u) {
                int ih = __shfl_sync(0xffffffffu, idx, h);
                FsW[h * 32 + lane] = f2[(size_t)ih * 32 + lane];
            }
        }
        __syncwarp();

        #pragma unroll
        for (int k = 0; k < KP; k++) {
            float ax = 0.0f, ay = 0.0f;
            unsigned mm = m[k];
            while (mm) {
                int h = __ffs(mm) - 1;
                mm &= mm - 1;
                float wk = __shfl_sync(0xffffffffu, w[k], h);
                float2 f = FsW[h * 32 + lane];
                ax = fmaf(wk, f.x, ax);
                ay = fmaf(wk, f.y, ay);
            }
            outp[(size_t)q * (KC / 2) + k * 32 + lane] = __floats2half2_rn(ax, ay);
        }
    }
}

// ---------------------------------------------------------------------------
// Kernel 2: GEMM out[N][128] = weighted[N][960] (f16) x wts[960][128] (f16)
// 128x128 tile, 8 warps (64x32 each), m16n8k16 HMMA, 2-stage cp.async pipeline.
// ---------------------------------------------------------------------------
__device__ __forceinline__ void ldm_x4(uint32_t& r0, uint32_t& r1,
                                       uint32_t& r2, uint32_t& r3,
                                       uint32_t addr) {
    asm volatile("ldmatrix.sync.aligned.m8n8.x4.shared.b16 {%0,%1,%2,%3}, [%4];"
                 : "=r"(r0), "=r"(r1), "=r"(r2), "=r"(r3) : "r"(addr));
}
__device__ __forceinline__ void ldm_x4_t(uint32_t& r0, uint32_t& r1,
                                         uint32_t& r2, uint32_t& r3,
                                         uint32_t addr) {
    asm volatile("ldmatrix.sync.aligned.m8n8.x4.trans.shared.b16 {%0,%1,%2,%3}, [%4];"
                 : "=r"(r0), "=r"(r1), "=r"(r2), "=r"(r3) : "r"(addr));
}
__device__ __forceinline__ void mma16816(float& c0, float& c1, float& c2, float& c3,
                                         uint32_t a0, uint32_t a1, uint32_t a2, uint32_t a3,
                                         uint32_t b0, uint32_t b1) {
    asm volatile(
        "mma.sync.aligned.m16n8k16.row.col.f32.f16.f16.f32 "
        "{%0,%1,%2,%3}, {%4,%5,%6,%7}, {%8,%9}, {%0,%1,%2,%3};"
        : "+f"(c0), "+f"(c1), "+f"(c2), "+f"(c3)
        : "r"(a0), "r"(a1), "r"(a2), "r"(a3), "r"(b0), "r"(b1));
}
__device__ __forceinline__ void cp16(uint32_t dst, const void* src, bool pred) {
    int sz = pred ? 16 : 0;
    asm volatile("cp.async.cg.shared.global [%0], [%1], 16, %2;"
                 :: "r"(dst), "l"(src), "r"(sz) : "memory");
}

#define AS_STRIDE 48    // halves per A row (32 data + 16 pad)
#define BS_STRIDE 136   // halves per B row (128 data + 8 pad)
#define NKT (KC / 32)   // 30 k-iterations

__global__ void __launch_bounds__(256) gemm_kernel(float* __restrict__ out, int nq) {
    __shared__ __half As[2][128 * AS_STRIDE];
    __shared__ __half Bs[2][32 * BS_STRIDE];

    int tid  = threadIdx.x;
    int wid  = tid >> 5;
    int lane = tid & 31;
    int wm = wid >> 2;   // 0..1  (64 rows each)
    int wn = wid & 3;    // 0..3  (32 cols each)
    int m0 = blockIdx.x * 128;

    // Per-thread copy coordinates (2 chunks each for A and B)
    int arow[2], aseg[2], brow[2], bseg[2];
    #pragma unroll
    for (int i = 0; i < 2; i++) {
        int chunk = tid + i * 256;
        arow[i] = chunk >> 2;  aseg[i] = chunk & 3;
        brow[i] = chunk >> 4;  bseg[i] = chunk & 15;
    }

    float c[4][4][4];
    #pragma unroll
    for (int i = 0; i < 4; i++)
        #pragma unroll
        for (int j = 0; j < 4; j++)
            #pragma unroll
            for (int t = 0; t < 4; t++) c[i][j][t] = 0.0f;

    int lrow  = lane & 15;
    int lcolh = (lane >> 4) * 8;

    auto issue = [&](int kt) {
        int st = kt & 1;
        #pragma unroll
        for (int i = 0; i < 2; i++) {
            int rg = m0 + arow[i];
            bool ok = (rg < nq);
            const __half* src = g_weighted +
                (size_t)(ok ? rg : 0) * KC + kt * 32 + aseg[i] * 8;
            cp16(smem_u32(&As[st][arow[i] * AS_STRIDE + aseg[i] * 8]), src, ok);
        }
        #pragma unroll
        for (int i = 0; i < 2; i++) {
            const __half* src = g_wts + (kt * 32 + brow[i]) * COUT + bseg[i] * 8;
            cp16(smem_u32(&Bs[st][brow[i] * BS_STRIDE + bseg[i] * 8]), src, true);
        }
    };

    issue(0);
    asm volatile("cp.async.commit_group;" ::: "memory");

    for (int kt = 0; kt < NKT; kt++) {
        if (kt + 1 < NKT) issue(kt + 1);
        asm volatile("cp.async.commit_group;" ::: "memory");
        asm volatile("cp.async.wait_group 1;" ::: "memory");
        __syncthreads();

        int st = kt & 1;
        #pragma unroll
        for (int ks = 0; ks < 2; ks++) {
            uint32_t a[4][4], b[4][2];
            #pragma unroll
            for (int im = 0; im < 4; im++) {
                uint32_t addr = smem_u32(
                    &As[st][(wm * 64 + im * 16 + lrow) * AS_STRIDE + ks * 16 + lcolh]);
                ldm_x4(a[im][0], a[im][1], a[im][2], a[im][3], addr);
            }
            #pragma unroll
            for (int ip = 0; ip < 2; ip++) {
                uint32_t addr = smem_u32(
                    &Bs[st][(ks * 16 + lrow) * BS_STRIDE + wn * 32 + ip * 16 + lcolh]);
                uint32_t r0, r1, r2, r3;
                ldm_x4_t(r0, r1, r2, r3, addr);
                b[ip * 2 + 0][0] = r0; b[ip * 2 + 0][1] = r1;
                b[ip * 2 + 1][0] = r2; b[ip * 2 + 1][1] = r3;
            }
            #pragma unroll
            for (int im = 0; im < 4; im++)
                #pragma unroll
                for (int in = 0; in < 4; in++)
                    mma16816(c[im][in][0], c[im][in][1], c[im][in][2], c[im][in][3],
                             a[im][0], a[im][1], a[im][2], a[im][3],
                             b[in][0], b[in][1]);
        }
        __syncthreads();
    }

    // Epilogue
    int gid = lane >> 2, tig = lane & 3;
    #pragma unroll
    for (int im = 0; im < 4; im++) {
        #pragma unroll
        for (int in = 0; in < 4; in++) {
            int row = m0 + wm * 64 + im * 16 + gid;
            int col = wn * 32 + in * 8 + tig * 2;
            if (row < nq) {
                float2 v0 = make_float2(c[im][in][0], c[im][in][1]);
                *(float2*)(out + (size_t)row * COUT + col) = v0;
            }
            if (row + 8 < nq) {
                float2 v1 = make_float2(c[im][in][2], c[im][in][3]);
                *(float2*)(out + (size_t)(row + 8) * COUT + col) = v1;
            }
        }
    }
}

// ---------------------------------------------------------------------------
extern "C" void kernel_launch(void* const* d_in, const int* in_sizes, int n_in,
                              void* d_out, int out_size) {
    const float* qp = (const float*)d_in[0];   // query_points   [N,3]
    const float* sp = (const float*)d_in[1];   // support_points [M,3]
    const int*   ni = (const int*)  d_in[2];   // neighbors_idx  [N,32]
    const float* ft = (const float*)d_in[3];   // features       [M,64]
    const float* kp = (const float*)d_in[4];   // kernel_points  [15,3]
    const float* wt = (const float*)d_in[5];   // wts            [15,64,128]
    float* out = (float*)d_out;

    int nq = in_sizes[0] / 3;

    // weight_kernel first => it is the kernel ncu captures.
    weight_kernel<<<(nq + 15) / 16, 128>>>(qp, sp, ni, ft, kp, nq);
    convert_wts_kernel<<<(KC * COUT + 255) / 256, 256>>>(wt);
    gemm_kernel<<<(nq + 127) / 128, 256>>>(out, nq);
}

// round 6
// speedup vs baseline: 1.9818x; 1.2901x over previous
#include <cuda_runtime.h>
#include <cuda_fp16.h>
#include <stdint.h>

// Problem constants (fixed by setup_inputs)
#define NQ   100000
#define HN   32      // neighbors per query
#define KP   15      // kernel points
#define CIN  64
#define COUT 128
#define KC   (KP * CIN)   // 960
#define KP_EXT 1.2f
#define KP_EXT2 (KP_EXT * KP_EXT)   // 1.44

// Scratch (device globals: allocation-free)
__device__ __half g_weighted[(size_t)NQ * KC];   // [N][K*Cin] fp16, ~192 MB
__device__ __half g_wts[KC * COUT];              // [K*Cin][Cout] fp16

__device__ __forceinline__ uint32_t smem_u32(const void* p) {
    uint32_t a;
    asm("{ .reg .u64 t; cvta.to.shared.u64 t, %1; cvt.u32.u64 %0, t; }"
        : "=r"(a) : "l"(p));
    return a;
}

// ---------------------------------------------------------------------------
// Kernel 0: convert wts fp32 -> fp16
// ---------------------------------------------------------------------------
__global__ void convert_wts_kernel(const float* __restrict__ wts) {
    int i = blockIdx.x * blockDim.x + threadIdx.x;
    if (i < KC * COUT) g_wts[i] = __float2half(wts[i]);
}

// ---------------------------------------------------------------------------
// Kernel 1: weights + sparse weighted feature aggregation.
// fp16 feature staging (16KB/block) -> ~2x occupancy vs round 5 (33KB).
// Accumulation kept in fp32 (only features are fp16-quantized).
// ---------------------------------------------------------------------------
__global__ void __launch_bounds__(128, 10) weight_kernel(
    const float* __restrict__ qpts,
    const float* __restrict__ spts,
    const int*   __restrict__ nidx,
    const float* __restrict__ feats,
    const float* __restrict__ kpts,
    int nq)
{
    __shared__ __half2 Fs[4][HN * 32];  // [warp][h][c-pair]  4*4KB = 16KB
    __shared__ float4 skp[KP];          // (kx, ky, kz, |kp|^2)

    int tid = threadIdx.x;
    if (tid < KP) {
        float kx = kpts[3 * tid + 0];
        float ky = kpts[3 * tid + 1];
        float kz = kpts[3 * tid + 2];
        skp[tid] = make_float4(kx, ky, kz, kx * kx + ky * ky + kz * kz);
    }
    __syncthreads();

    int warp = tid >> 5;
    int lane = tid & 31;
    const float inv_ext = 1.0f / KP_EXT;
    int qbase = blockIdx.x * 16 + warp * 4;

    const float2* __restrict__ f2 = (const float2*)feats;
    __half2* FsW = Fs[warp];
    __half2* outp = (__half2*)g_weighted;

    #pragma unroll 1
    for (int qi = 0; qi < 4; qi++) {
        int q = qbase + qi;
        if (q >= nq) return;   // warp-uniform

        // ---- weights: lane owns neighbor h = lane ----
        int idx = nidx[q * HN + lane];
        float qx = qpts[q * 3 + 0];
        float qy = qpts[q * 3 + 1];
        float qz = qpts[q * 3 + 2];
        float px = spts[idx * 3 + 0] - qx;
        float py = spts[idx * 3 + 1] - qy;
        float pz = spts[idx * 3 + 2] - qz;
        float pp = px * px + py * py + pz * pz;

        float    w[KP];
        unsigned m[KP];
        unsigned active_h = 0;
        #pragma unroll
        for (int k = 0; k < KP; k++) {
            float4 kv = skp[k];
            float t  = fmaf(px, kv.x, fmaf(py, kv.y, pz * kv.z));
            float d2 = fmaf(-2.0f, t, pp + kv.w);
            float wv = 0.0f;
            if (d2 < KP_EXT2)
                wv = 1.0f - sqrtf(fmaxf(d2, 0.0f)) * inv_ext;
            w[k] = wv;
            m[k] = __ballot_sync(0xffffffffu, wv > 0.0f);
            active_h |= m[k];
        }

        // ---- Phase A: stage active neighbor features to smem (fp16) ----
        __syncwarp();
        #pragma unroll
        for (int h = 0; h < HN; h++) {
            if ((active_h >> h) & 1u) {               // warp-uniform predicate
                int ih = __shfl_sync(0xffffffffu, idx, h);
                float2 f = f2[(size_t)ih * 32 + lane];
                FsW[h * 32 + lane] = __floats2half2_rn(f.x, f.y);
            }
        }
        __syncwarp();

        // ---- Phase B: sparse per-k accumulation (fp32 acc) ----
        #pragma unroll
        for (int k = 0; k < KP; k++) {
            float ax = 0.0f, ay = 0.0f;
            unsigned mm = m[k];
            while (mm) {
                int h = __ffs(mm) - 1;
                mm &= mm - 1;
                float wk = __shfl_sync(0xffffffffu, w[k], h);
                float2 f = __half22float2(FsW[h * 32 + lane]);
                ax = fmaf(wk, f.x, ax);
                ay = fmaf(wk, f.y, ay);
            }
            outp[(size_t)q * (KC / 2) + k * 32 + lane] = __floats2half2_rn(ax, ay);
        }
    }
}

// ---------------------------------------------------------------------------
// Kernel 2: GEMM out[N][128] = weighted[N][960] (f16) x wts[960][128] (f16)
// 128x128 tile, 8 warps (64x32 each), m16n8k16 HMMA, 2-stage cp.async pipeline.
// ---------------------------------------------------------------------------
__device__ __forceinline__ void ldm_x4(uint32_t& r0, uint32_t& r1,
                                       uint32_t& r2, uint32_t& r3,
                                       uint32_t addr) {
    asm volatile("ldmatrix.sync.aligned.m8n8.x4.shared.b16 {%0,%1,%2,%3}, [%4];"
                 : "=r"(r0), "=r"(r1), "=r"(r2), "=r"(r3) : "r"(addr));
}
__device__ __forceinline__ void ldm_x4_t(uint32_t& r0, uint32_t& r1,
                                         uint32_t& r2, uint32_t& r3,
                                         uint32_t addr) {
    asm volatile("ldmatrix.sync.aligned.m8n8.x4.trans.shared.b16 {%0,%1,%2,%3}, [%4];"
                 : "=r"(r0), "=r"(r1), "=r"(r2), "=r"(r3) : "r"(addr));
}
__device__ __forceinline__ void mma16816(float& c0, float& c1, float& c2, float& c3,
                                         uint32_t a0, uint32_t a1, uint32_t a2, uint32_t a3,
                                         uint32_t b0, uint32_t b1) {
    asm volatile(
        "mma.sync.aligned.m16n8k16.row.col.f32.f16.f16.f32 "
        "{%0,%1,%2,%3}, {%4,%5,%6,%7}, {%8,%9}, {%0,%1,%2,%3};"
        : "+f"(c0), "+f"(c1), "+f"(c2), "+f"(c3)
        : "r"(a0), "r"(a1), "r"(a2), "r"(a3), "r"(b0), "r"(b1));
}
__device__ __forceinline__ void cp16(uint32_t dst, const void* src, bool pred) {
    int sz = pred ? 16 : 0;
    asm volatile("cp.async.cg.shared.global [%0], [%1], 16, %2;"
                 :: "r"(dst), "l"(src), "r"(sz) : "memory");
}

#define AS_STRIDE 48    // halves per A row (32 data + 16 pad)
#define BS_STRIDE 136   // halves per B row (128 data + 8 pad)
#define NKT (KC / 32)   // 30 k-iterations

__global__ void __launch_bounds__(256) gemm_kernel(float* __restrict__ out, int nq) {
    __shared__ __half As[2][128 * AS_STRIDE];
    __shared__ __half Bs[2][32 * BS_STRIDE];

    int tid  = threadIdx.x;
    int wid  = tid >> 5;
    int lane = tid & 31;
    int wm = wid >> 2;   // 0..1  (64 rows each)
    int wn = wid & 3;    // 0..3  (32 cols each)
    int m0 = blockIdx.x * 128;

    int arow[2], aseg[2], brow[2], bseg[2];
    #pragma unroll
    for (int i = 0; i < 2; i++) {
        int chunk = tid + i * 256;
        arow[i] = chunk >> 2;  aseg[i] = chunk & 3;
        brow[i] = chunk >> 4;  bseg[i] = chunk & 15;
    }

    float c[4][4][4];
    #pragma unroll
    for (int i = 0; i < 4; i++)
        #pragma unroll
        for (int j = 0; j < 4; j++)
            #pragma unroll
            for (int t = 0; t < 4; t++) c[i][j][t] = 0.0f;

    int lrow  = lane & 15;
    int lcolh = (lane >> 4) * 8;

    auto issue = [&](int kt) {
        int st = kt & 1;
        #pragma unroll
        for (int i = 0; i < 2; i++) {
            int rg = m0 + arow[i];
            bool ok = (rg < nq);
            const __half* src = g_weighted +
                (size_t)(ok ? rg : 0) * KC + kt * 32 + aseg[i] * 8;
            cp16(smem_u32(&As[st][arow[i] * AS_STRIDE + aseg[i] * 8]), src, ok);
        }
        #pragma unroll
        for (int i = 0; i < 2; i++) {
            const __half* src = g_wts + (kt * 32 + brow[i]) * COUT + bseg[i] * 8;
            cp16(smem_u32(&Bs[st][brow[i] * BS_STRIDE + bseg[i] * 8]), src, true);
        }
    };

    issue(0);
    asm volatile("cp.async.commit_group;" ::: "memory");

    for (int kt = 0; kt < NKT; kt++) {
        if (kt + 1 < NKT) issue(kt + 1);
        asm volatile("cp.async.commit_group;" ::: "memory");
        asm volatile("cp.async.wait_group 1;" ::: "memory");
        __syncthreads();

        int st = kt & 1;
        #pragma unroll
        for (int ks = 0; ks < 2; ks++) {
            uint32_t a[4][4], b[4][2];
            #pragma unroll
            for (int im = 0; im < 4; im++) {
                uint32_t addr = smem_u32(
                    &As[st][(wm * 64 + im * 16 + lrow) * AS_STRIDE + ks * 16 + lcolh]);
                ldm_x4(a[im][0], a[im][1], a[im][2], a[im][3], addr);
            }
            #pragma unroll
            for (int ip = 0; ip < 2; ip++) {
                uint32_t addr = smem_u32(
                    &Bs[st][(ks * 16 + lrow) * BS_STRIDE + wn * 32 + ip * 16 + lcolh]);
                uint32_t r0, r1, r2, r3;
                ldm_x4_t(r0, r1, r2, r3, addr);
                b[ip * 2 + 0][0] = r0; b[ip * 2 + 0][1] = r1;
                b[ip * 2 + 1][0] = r2; b[ip * 2 + 1][1] = r3;
            }
            #pragma unroll
            for (int im = 0; im < 4; im++)
                #pragma unroll
                for (int in = 0; in < 4; in++)
                    mma16816(c[im][in][0], c[im][in][1], c[im][in][2], c[im][in][3],
                             a[im][0], a[im][1], a[im][2], a[im][3],
                             b[in][0], b[in][1]);
        }
        __syncthreads();
    }

    // Epilogue
    int gid = lane >> 2, tig = lane & 3;
    #pragma unroll
    for (int im = 0; im < 4; im++) {
        #pragma unroll
        for (int in = 0; in < 4; in++) {
            int row = m0 + wm * 64 + im * 16 + gid;
            int col = wn * 32 + in * 8 + tig * 2;
            if (row < nq) {
                float2 v0 = make_float2(c[im][in][0], c[im][in][1]);
                *(float2*)(out + (size_t)row * COUT + col) = v0;
            }
            if (row + 8 < nq) {
                float2 v1 = make_float2(c[im][in][2], c[im][in][3]);
                *(float2*)(out + (size_t)(row + 8) * COUT + col) = v1;
            }
        }
    }
}

// ---------------------------------------------------------------------------
extern "C" void kernel_launch(void* const* d_in, const int* in_sizes, int n_in,
                              void* d_out, int out_size) {
    const float* qp = (const float*)d_in[0];   // query_points   [N,3]
    const float* sp = (const float*)d_in[1];   // support_points [M,3]
    const int*   ni = (const int*)  d_in[2];   // neighbors_idx  [N,32]
    const float* ft = (const float*)d_in[3];   // features       [M,64]
    const float* kp = (const float*)d_in[4];   // kernel_points  [15,3]
    const float* wt = (const float*)d_in[5];   // wts            [15,64,128]
    float* out = (float*)d_out;

    int nq = in_sizes[0] / 3;

    // weight_kernel first => it is the kernel ncu captures.
    weight_kernel<<<(nq + 15) / 16, 128>>>(qp, sp, ni, ft, kp, nq);
    convert_wts_kernel<<<(KC * COUT + 255) / 256, 256>>>(wt);
    gemm_kernel<<<(nq + 127) / 128, 256>>>(out, nq);
}